// round 5
// baseline (speedup 1.0000x reference)
#include <cuda_runtime.h>
#include <math.h>

#define HID   1024
#define BATCH 32
#define SEQ   2048
#define EDIM  2048           // 2*HID
#define ROWS  (BATCH*SEQ)    // 65536

// ---- scratch (no allocations allowed) ----
__device__ float g_hid_proj[BATCH * HID];
__device__ float g_scores[BATCH * SEQ];

// ============================================================
// Kernel 1: hid_proj[b,h] = sum_k hidden[b,k] * attn_w[h, k] + attn_b[h]
// grid (HID/8, BATCH), block 256 (8 warps, 1 warp per h)
// ============================================================
__global__ void hidproj_kernel(const float* __restrict__ hidden,
                               const float* __restrict__ attn_w,
                               const float* __restrict__ attn_b) {
    int b    = blockIdx.y;
    int warp = threadIdx.x >> 5;
    int lane = threadIdx.x & 31;
    int h    = blockIdx.x * 8 + warp;

    const float4* hv = (const float4*)(hidden + (size_t)b * HID);
    const float4* wv = (const float4*)(attn_w + (size_t)h * (3 * HID));

    float s = 0.f;
#pragma unroll
    for (int i = 0; i < HID / 4 / 32; i++) {   // 8 iterations
        float4 a = hv[lane + i * 32];
        float4 w = wv[lane + i * 32];
        s += a.x * w.x + a.y * w.y + a.z * w.z + a.w * w.w;
    }
#pragma unroll
    for (int o = 16; o; o >>= 1) s += __shfl_xor_sync(0xffffffffu, s, o);
    if (lane == 0) g_hid_proj[b * HID + h] = s + attn_b[h];
}

// ============================================================
// Kernel 2: zero the score accumulators
// ============================================================
__global__ void zero_scores_kernel() {
    g_scores[blockIdx.x * 1024 + threadIdx.x] = 0.f;
}

// ============================================================
// Kernel 3: scores GEMM (the big one)
//   C[row, h] = enc[row,:] (K=2048) dot w_e[h,:]    (w_e = attn_w[:, HID:3*HID])
//   then: score_partial[row] += sum_h v_w[h] * tanh(hid_proj[b,h] + C[row,h])
// Tiling: BM=128 rows, BN=128 h-cols, BK=16; 256 threads, 8x8 microtile.
// grid (8 n-tiles [x, fast — keeps A-tile sharers co-resident], 512 row-tiles [y])
// ============================================================
#define BM 128
#define BN 128
#define BK 16
#define PAD 4   // row stride 132 floats = 528 B (16B multiple -> aligned float4 reads)

__global__ __launch_bounds__(256, 2)
void scores_kernel(const float* __restrict__ enc,
                   const float* __restrict__ attn_w,
                   const float* __restrict__ v_w) {
    __shared__ float As[BK][BM + PAD];   // transposed: As[k][m]
    __shared__ float Bs[BK][BN + PAD];   // transposed: Bs[k][n]
    __shared__ float ssc[BM];
    __shared__ float hp_s[BN];
    __shared__ float vw_s[BN];

    const int nt = blockIdx.x;           // 0..7
    const int rt = blockIdx.y;           // 0..511
    const int b  = rt >> 4;              // 16 row-tiles per batch (2048/128)
    const int s0 = (rt & 15) * BM;
    const int nb = nt * BN;

    const int tid = threadIdx.x;
    if (tid < BM) ssc[tid] = 0.f;
    if (tid < BN) {
        hp_s[tid] = g_hid_proj[b * HID + nb + tid];
        vw_s[tid] = v_w[nb + tid];
    }

    const int m0 = (tid >> 4) * 8;       // output rows for this thread
    const int n0 = (tid & 15) * 8;       // output cols for this thread

    // load mapping: 256 threads, float4 along K
    const int lr = tid >> 2;             // 0..63
    const int lk = (tid & 3) * 4;        // 0,4,8,12

    const float* Ag = enc + (size_t)rt * BM * EDIM;  // 128 contiguous rows of length EDIM
    const float* Bg = attn_w + HID;                  // w_e: row h at stride 3*HID

    float acc[8][8];
#pragma unroll
    for (int i = 0; i < 8; i++)
#pragma unroll
        for (int j = 0; j < 8; j++) acc[i][j] = 0.f;

    for (int k0 = 0; k0 < EDIM; k0 += BK) {
        __syncthreads();   // protect smem from previous iteration's readers
#pragma unroll
        for (int p = 0; p < 2; p++) {
            int m = lr + p * 64;
            float4 v = *(const float4*)&Ag[(size_t)m * EDIM + k0 + lk];
            As[lk + 0][m] = v.x; As[lk + 1][m] = v.y;
            As[lk + 2][m] = v.z; As[lk + 3][m] = v.w;
        }
#pragma unroll
        for (int p = 0; p < 2; p++) {
            int n = lr + p * 64;
            float4 v = *(const float4*)&Bg[(size_t)(nb + n) * (3 * HID) + k0 + lk];
            Bs[lk + 0][n] = v.x; Bs[lk + 1][n] = v.y;
            Bs[lk + 2][n] = v.z; Bs[lk + 3][n] = v.w;
        }
        __syncthreads();

#pragma unroll
        for (int k = 0; k < BK; k++) {
            float4 a0 = *(const float4*)&As[k][m0];
            float4 a1 = *(const float4*)&As[k][m0 + 4];
            float4 b0 = *(const float4*)&Bs[k][n0];
            float4 b1 = *(const float4*)&Bs[k][n0 + 4];
            float a[8]  = {a0.x, a0.y, a0.z, a0.w, a1.x, a1.y, a1.z, a1.w};
            float bb[8] = {b0.x, b0.y, b0.z, b0.w, b1.x, b1.y, b1.z, b1.w};
#pragma unroll
            for (int i = 0; i < 8; i++)
#pragma unroll
                for (int j = 0; j < 8; j++)
                    acc[i][j] += a[i] * bb[j];
        }
    }

    __syncthreads();   // last readers done; ssc zero visible

    // epilogue: tanh + v-weighted reduction over this thread's 8 columns
#pragma unroll
    for (int i = 0; i < 8; i++) {
        float p = 0.f;
#pragma unroll
        for (int j = 0; j < 8; j++) {
            float e = tanhf(hp_s[n0 + j] + acc[i][j]);
            p += vw_s[n0 + j] * e;
        }
        atomicAdd(&ssc[m0 + i], p);
    }
    __syncthreads();
    if (tid < BM) atomicAdd(&g_scores[b * SEQ + s0 + tid], ssc[tid]);
}

// ============================================================
// Kernel 4: softmax over S per batch -> attention weights
// grid BATCH, block 256 (8 elements/thread)
// ============================================================
__global__ void softmax_kernel(float* __restrict__ out_w) {
    __shared__ float red[256];
    int b = blockIdx.x;
    int tid = threadIdx.x;

    float vals[8];
    float mx = -1e30f;
#pragma unroll
    for (int i = 0; i < 8; i++) {
        vals[i] = g_scores[b * SEQ + tid + i * 256];
        mx = fmaxf(mx, vals[i]);
    }
    red[tid] = mx;
    __syncthreads();
    for (int o = 128; o; o >>= 1) {
        if (tid < o) red[tid] = fmaxf(red[tid], red[tid + o]);
        __syncthreads();
    }
    mx = red[0];
    __syncthreads();

    float s = 0.f;
#pragma unroll
    for (int i = 0; i < 8; i++) {
        vals[i] = expf(vals[i] - mx);
        s += vals[i];
    }
    red[tid] = s;
    __syncthreads();
    for (int o = 128; o; o >>= 1) {
        if (tid < o) red[tid] += red[tid + o];
        __syncthreads();
    }
    float inv = 1.f / red[0];
#pragma unroll
    for (int i = 0; i < 8; i++)
        out_w[b * SEQ + tid + i * 256] = vals[i] * inv;
}

// ============================================================
// Kernel 5: context[b,e] = sum_s w[b,s] * enc[b,s,e]
// grid (EDIM/256, BATCH), block 256
// ============================================================
__global__ void context_kernel(const float* __restrict__ enc,
                               const float* __restrict__ w,
                               float* __restrict__ outc) {
    __shared__ float ws[SEQ];
    int b = blockIdx.y;
    int e = blockIdx.x * 256 + threadIdx.x;

    for (int i = threadIdx.x; i < SEQ; i += 256) ws[i] = w[b * SEQ + i];
    __syncthreads();

    const float* ep = enc + (size_t)b * SEQ * EDIM + e;
    float a0 = 0.f, a1 = 0.f, a2 = 0.f, a3 = 0.f;
    for (int s = 0; s < SEQ; s += 4) {
        a0 += ws[s + 0] * ep[(size_t)(s + 0) * EDIM];
        a1 += ws[s + 1] * ep[(size_t)(s + 1) * EDIM];
        a2 += ws[s + 2] * ep[(size_t)(s + 2) * EDIM];
        a3 += ws[s + 3] * ep[(size_t)(s + 3) * EDIM];
    }
    outc[b * EDIM + e] = (a0 + a1) + (a2 + a3);
}

// ============================================================
// launch: inputs are hidden, encoder_outputs, attn_w, attn_b, v_w
// output: context (32*2048) then attention_weights (32*2048)
// ============================================================
extern "C" void kernel_launch(void* const* d_in, const int* in_sizes, int n_in,
                              void* d_out, int out_size) {
    const float* hidden = (const float*)d_in[0];
    const float* enc    = (const float*)d_in[1];
    const float* attn_w = (const float*)d_in[2];
    const float* attn_b = (const float*)d_in[3];
    const float* v_w    = (const float*)d_in[4];

    float* out_ctx = (float*)d_out;                  // [32, 2048]
    float* out_wts = (float*)d_out + BATCH * EDIM;   // [32, 2048]

    hidproj_kernel<<<dim3(HID / 8, BATCH), 256>>>(hidden, attn_w, attn_b);
    zero_scores_kernel<<<(BATCH * SEQ) / 1024, 1024>>>();
    scores_kernel<<<dim3(HID / BN, ROWS / BM), 256>>>(enc, attn_w, v_w);
    softmax_kernel<<<BATCH, 256>>>(out_wts);
    context_kernel<<<dim3(EDIM / 256, BATCH), 256>>>(enc, out_wts, out_ctx);
}

// round 7
// speedup vs baseline: 3.1489x; 3.1489x over previous
#include <cuda_runtime.h>
#include <math.h>
#include <stdint.h>

#define HID   1024
#define BATCH 32
#define SEQ   2048
#define EDIM  2048           // 2*HID
#define ROWS  (BATCH*SEQ)    // 65536

// ---- scratch (no allocations allowed) ----
__device__ float g_hid_proj[BATCH * HID];
__device__ float g_scores[BATCH * SEQ];

// ============================================================
// helpers
// ============================================================
__device__ __forceinline__ uint32_t smem_u32(const void* p) {
    uint32_t a;
    asm("{ .reg .u64 t; cvta.to.shared.u64 t, %1; cvt.u32.u64 %0, t; }" : "=r"(a) : "l"(p));
    return a;
}
__device__ __forceinline__ uint32_t f2tf32(float x) {
    uint32_t r;
    asm("cvt.rna.tf32.f32 %0, %1;" : "=r"(r) : "f"(x));
    return r;
}
__device__ __forceinline__ void cp16(uint32_t dst, const void* src) {
    asm volatile("cp.async.cg.shared.global [%0], [%1], 16;" :: "r"(dst), "l"(src));
}
__device__ __forceinline__ void cp_commit() {
    asm volatile("cp.async.commit_group;" ::: "memory");
}
__device__ __forceinline__ void cp_wait1() {
    asm volatile("cp.async.wait_group 1;" ::: "memory");
}
__device__ __forceinline__ void mma1688(float* c, const uint32_t* a, uint32_t b0, uint32_t b1) {
    asm volatile(
        "mma.sync.aligned.m16n8k8.row.col.f32.tf32.tf32.f32 "
        "{%0,%1,%2,%3}, {%4,%5,%6,%7}, {%8,%9}, {%0,%1,%2,%3};"
        : "+f"(c[0]), "+f"(c[1]), "+f"(c[2]), "+f"(c[3])
        : "r"(a[0]), "r"(a[1]), "r"(a[2]), "r"(a[3]), "r"(b0), "r"(b1));
}

// ============================================================
// Kernel 1: hid_proj[b,h] = hidden[b,:] . attn_w[h, 0:H] + attn_b[h]
// ============================================================
__global__ void hidproj_kernel(const float* __restrict__ hidden,
                               const float* __restrict__ attn_w,
                               const float* __restrict__ attn_b) {
    int b    = blockIdx.y;
    int warp = threadIdx.x >> 5;
    int lane = threadIdx.x & 31;
    int h    = blockIdx.x * 8 + warp;

    const float4* hv = (const float4*)(hidden + (size_t)b * HID);
    const float4* wv = (const float4*)(attn_w + (size_t)h * (3 * HID));

    float s = 0.f;
#pragma unroll
    for (int i = 0; i < HID / 4 / 32; i++) {
        float4 a = hv[lane + i * 32];
        float4 w = wv[lane + i * 32];
        s += a.x * w.x + a.y * w.y + a.z * w.z + a.w * w.w;
    }
#pragma unroll
    for (int o = 16; o; o >>= 1) s += __shfl_xor_sync(0xffffffffu, s, o);
    if (lane == 0) g_hid_proj[b * HID + h] = s + attn_b[h];
}

// ============================================================
// Kernel 2: zero scores
// ============================================================
__global__ void zero_scores_kernel() {
    g_scores[blockIdx.x * 1024 + threadIdx.x] = 0.f;
}

// ============================================================
// Kernel 3: scores via mma.sync tf32, fused tanh + v-dot epilogue
//   C[row, h] = enc[row,:] . w_e[h,:]   (K=2048)
//   g_scores[row] += sum_h v_w[h] * tanh(hid_proj[b,h] + C[row,h])
// BM=128, BN=128, BK=32. 256 threads (8 warps, 2x4), warp tile 64x32.
// cp.async double-buffered fp32 smem; cvt.rna.tf32 at fragment load.
// ============================================================
#define BM  128
#define BN  128
#define BKK 32
#define NKT (EDIM / BKK)     // 64
#define LDA 36               // padded row length in words (conflict-free frags)

#define SM_A0  0
#define SM_A1  18432         // 128*36*4
#define SM_B0  36864
#define SM_B1  55296
#define SM_HP  73728         // 128 floats
#define SM_VW  74240
#define SM_SSC 74752
#define SM_SZ  75264

__global__ __launch_bounds__(256, 2)
void scores_mma_kernel(const float* __restrict__ enc,
                       const float* __restrict__ attn_w,
                       const float* __restrict__ v_w) {
    extern __shared__ char smem[];
    const uint32_t sb = smem_u32(smem);

    const int tid    = threadIdx.x;
    const int lane   = tid & 31;
    const int wid    = tid >> 5;
    const int warp_m = wid & 1;          // 0..1  (64 rows each)
    const int warp_n = wid >> 1;         // 0..3  (32 cols each)

    const int rt     = blockIdx.y;       // 0..511
    const int b      = rt >> 4;
    const int nb     = blockIdx.x * BN;  // 0..7 n-tiles
    const int m_base = rt * BM;

    const float* w_e = attn_w + HID;

    float* hp_s = (float*)(smem + SM_HP);
    float* vw_s = (float*)(smem + SM_VW);
    float* ssc  = (float*)(smem + SM_SSC);
    if (tid < BN) {
        hp_s[tid] = g_hid_proj[b * HID + nb + tid];
        vw_s[tid] = v_w[nb + tid];
    }
    if (tid < BM) ssc[tid] = 0.f;

    const uint32_t aOff[2] = { sb + SM_A0, sb + SM_A1 };
    const uint32_t bOff[2] = { sb + SM_B0, sb + SM_B1 };

    // staging map: idx = tid + i*256 -> row = idx>>3, c4 = idx&7 (float4 along k)
    const int srow = tid >> 3;           // base row for i=0 (rows advance by 32/i)
    const int sc4  = tid & 7;

    // prologue: stage k-tile 0 into buffer 0
    {
        const float* ag = enc + (size_t)m_base * EDIM + sc4 * 4;
        const float* bg = w_e + (size_t)nb * (3 * HID) + sc4 * 4;
#pragma unroll
        for (int i = 0; i < 4; i++) {
            int row = srow + i * 32;
            cp16(aOff[0] + (row * LDA + sc4 * 4) * 4, ag + (size_t)row * EDIM);
            cp16(bOff[0] + (row * LDA + sc4 * 4) * 4, bg + (size_t)row * (3 * HID));
        }
        cp_commit();
    }

    float acc[4][4][4];
#pragma unroll
    for (int mt = 0; mt < 4; mt++)
#pragma unroll
        for (int nt = 0; nt < 4; nt++)
#pragma unroll
            for (int j = 0; j < 4; j++) acc[mt][nt][j] = 0.f;

    for (int kt = 0; kt < NKT; kt++) {
        const int cur = kt & 1;
        // prefetch next k-tile into other buffer
        if (kt < NKT - 1) {
            const int k0 = (kt + 1) * BKK;
            const float* ag = enc + (size_t)m_base * EDIM + k0 + sc4 * 4;
            const float* bg = w_e + (size_t)nb * (3 * HID) + k0 + sc4 * 4;
#pragma unroll
            for (int i = 0; i < 4; i++) {
                int row = srow + i * 32;
                cp16(aOff[1 - cur] + (row * LDA + sc4 * 4) * 4, ag + (size_t)row * EDIM);
                cp16(bOff[1 - cur] + (row * LDA + sc4 * 4) * 4, bg + (size_t)row * (3 * HID));
            }
        }
        cp_commit();            // empty group on last iter keeps wait uniform
        cp_wait1();             // group for 'cur' is complete
        __syncthreads();

        const float* Ac = (const float*)(smem + (cur ? SM_A1 : SM_A0));
        const float* Bc = (const float*)(smem + (cur ? SM_B1 : SM_B0));

#pragma unroll
        for (int kk = 0; kk < 4; kk++) {
            const int kcol = kk * 8 + (lane & 3);
            uint32_t a[4][4];
#pragma unroll
            for (int mt = 0; mt < 4; mt++) {
                int r = warp_m * 64 + mt * 16 + (lane >> 2);
                a[mt][0] = f2tf32(Ac[r * LDA + kcol]);
                a[mt][1] = f2tf32(Ac[(r + 8) * LDA + kcol]);
                a[mt][2] = f2tf32(Ac[r * LDA + kcol + 4]);
                a[mt][3] = f2tf32(Ac[(r + 8) * LDA + kcol + 4]);
            }
#pragma unroll
            for (int nt = 0; nt < 4; nt++) {
                int n = warp_n * 32 + nt * 8 + (lane >> 2);
                uint32_t b0 = f2tf32(Bc[n * LDA + kcol]);
                uint32_t b1 = f2tf32(Bc[n * LDA + kcol + 4]);
#pragma unroll
                for (int mt = 0; mt < 4; mt++)
                    mma1688(acc[mt][nt], a[mt], b0, b1);
            }
        }
        __syncthreads();        // done reading 'cur' before it is restaged
    }

    // ---- epilogue: tanh + v-dot, quad reduce, shared then global atomics ----
#pragma unroll
    for (int mt = 0; mt < 4; mt++) {
        float p0 = 0.f, p1 = 0.f;
#pragma unroll
        for (int nt = 0; nt < 4; nt++) {
            int c0 = warp_n * 32 + nt * 8 + 2 * (lane & 3);
            float v0 = vw_s[c0], v1 = vw_s[c0 + 1];
            float h0 = hp_s[c0], h1 = hp_s[c0 + 1];
            p0 += v0 * tanhf(h0 + acc[mt][nt][0]) + v1 * tanhf(h1 + acc[mt][nt][1]);
            p1 += v0 * tanhf(h0 + acc[mt][nt][2]) + v1 * tanhf(h1 + acc[mt][nt][3]);
        }
        p0 += __shfl_xor_sync(0xffffffffu, p0, 1);
        p0 += __shfl_xor_sync(0xffffffffu, p0, 2);
        p1 += __shfl_xor_sync(0xffffffffu, p1, 1);
        p1 += __shfl_xor_sync(0xffffffffu, p1, 2);
        if ((lane & 3) == 0) {
            int r = warp_m * 64 + mt * 16 + (lane >> 2);
            atomicAdd(&ssc[r], p0);
            atomicAdd(&ssc[r + 8], p1);
        }
    }
    __syncthreads();
    if (tid < BM) atomicAdd(&g_scores[m_base + tid], ssc[tid]);
}

// ============================================================
// Kernel 4: softmax over S per batch
// ============================================================
__global__ void softmax_kernel(float* __restrict__ out_w) {
    __shared__ float red[256];
    int b = blockIdx.x;
    int tid = threadIdx.x;

    float vals[8];
    float mx = -1e30f;
#pragma unroll
    for (int i = 0; i < 8; i++) {
        vals[i] = g_scores[b * SEQ + tid + i * 256];
        mx = fmaxf(mx, vals[i]);
    }
    red[tid] = mx;
    __syncthreads();
    for (int o = 128; o; o >>= 1) {
        if (tid < o) red[tid] = fmaxf(red[tid], red[tid + o]);
        __syncthreads();
    }
    mx = red[0];
    __syncthreads();

    float s = 0.f;
#pragma unroll
    for (int i = 0; i < 8; i++) {
        vals[i] = expf(vals[i] - mx);
        s += vals[i];
    }
    red[tid] = s;
    __syncthreads();
    for (int o = 128; o; o >>= 1) {
        if (tid < o) red[tid] += red[tid + o];
        __syncthreads();
    }
    float inv = 1.f / red[0];
#pragma unroll
    for (int i = 0; i < 8; i++)
        out_w[b * SEQ + tid + i * 256] = vals[i] * inv;
}

// ============================================================
// Kernel 5: context[b,e] = sum_s w[b,s] * enc[b,s,e]
// ============================================================
__global__ void context_kernel(const float* __restrict__ enc,
                               const float* __restrict__ w,
                               float* __restrict__ outc) {
    __shared__ float ws[SEQ];
    int b = blockIdx.y;
    int e = blockIdx.x * 256 + threadIdx.x;

    for (int i = threadIdx.x; i < SEQ; i += 256) ws[i] = w[b * SEQ + i];
    __syncthreads();

    const float* ep = enc + (size_t)b * SEQ * EDIM + e;
    float a0 = 0.f, a1 = 0.f, a2 = 0.f, a3 = 0.f;
    for (int s = 0; s < SEQ; s += 4) {
        a0 += ws[s + 0] * ep[(size_t)(s + 0) * EDIM];
        a1 += ws[s + 1] * ep[(size_t)(s + 1) * EDIM];
        a2 += ws[s + 2] * ep[(size_t)(s + 2) * EDIM];
        a3 += ws[s + 3] * ep[(size_t)(s + 3) * EDIM];
    }
    outc[b * EDIM + e] = (a0 + a1) + (a2 + a3);
}

// ============================================================
// launch
// ============================================================
extern "C" void kernel_launch(void* const* d_in, const int* in_sizes, int n_in,
                              void* d_out, int out_size) {
    const float* hidden = (const float*)d_in[0];
    const float* enc    = (const float*)d_in[1];
    const float* attn_w = (const float*)d_in[2];
    const float* attn_b = (const float*)d_in[3];
    const float* v_w    = (const float*)d_in[4];

    float* out_ctx = (float*)d_out;                  // [32, 2048]
    float* out_wts = (float*)d_out + BATCH * EDIM;   // [32, 2048]

    cudaFuncSetAttribute(scores_mma_kernel,
                         cudaFuncAttributeMaxDynamicSharedMemorySize, SM_SZ);

    hidproj_kernel<<<dim3(HID / 8, BATCH), 256>>>(hidden, attn_w, attn_b);
    zero_scores_kernel<<<(BATCH * SEQ) / 1024, 1024>>>();
    scores_mma_kernel<<<dim3(HID / BN, ROWS / BM), 256, SM_SZ>>>(enc, attn_w, v_w);
    softmax_kernel<<<BATCH, 256>>>(out_wts);
    context_kernel<<<dim3(EDIM / 256, BATCH), 256>>>(enc, out_wts, out_ctx);
}

// round 8
// speedup vs baseline: 5.2690x; 1.6733x over previous
#include <cuda_runtime.h>
#include <cuda_bf16.h>
#include <math.h>
#include <stdint.h>

#define HID   1024
#define BATCH 32
#define SEQ   2048
#define EDIM  2048           // 2*HID
#define ROWS  (BATCH*SEQ)    // 65536

// ---- scratch (no allocations allowed) ----
__device__ float g_hid_proj[BATCH * HID];
__device__ float g_scores[BATCH * SEQ];
__device__ uint4 g_enc_bf16[(size_t)ROWS * EDIM / 8];   // 268 MB, bf16-packed
__device__ uint4 g_we_bf16[(size_t)HID * EDIM / 8];     // 4 MB, bf16-packed

// ============================================================
// helpers
// ============================================================
__device__ __forceinline__ uint32_t smem_u32(const void* p) {
    uint32_t a;
    asm("{ .reg .u64 t; cvta.to.shared.u64 t, %1; cvt.u32.u64 %0, t; }" : "=r"(a) : "l"(p));
    return a;
}
__device__ __forceinline__ void cp16(uint32_t dst, const void* src) {
    asm volatile("cp.async.cg.shared.global [%0], [%1], 16;" :: "r"(dst), "l"(src));
}
__device__ __forceinline__ void cp_commit() {
    asm volatile("cp.async.commit_group;" ::: "memory");
}
__device__ __forceinline__ void cp_wait1() {
    asm volatile("cp.async.wait_group 1;" ::: "memory");
}
__device__ __forceinline__ void mma16816(float* c, const uint32_t* a, uint32_t b0, uint32_t b1) {
    asm volatile(
        "mma.sync.aligned.m16n8k16.row.col.f32.bf16.bf16.f32 "
        "{%0,%1,%2,%3}, {%4,%5,%6,%7}, {%8,%9}, {%0,%1,%2,%3};"
        : "+f"(c[0]), "+f"(c[1]), "+f"(c[2]), "+f"(c[3])
        : "r"(a[0]), "r"(a[1]), "r"(a[2]), "r"(a[3]), "r"(b0), "r"(b1));
}
__device__ __forceinline__ uint32_t pack_bf16x2(float lo, float hi) {
    __nv_bfloat162 h = __floats2bfloat162_rn(lo, hi);   // x = lo (low 16 bits)
    return *(uint32_t*)&h;
}

// ============================================================
// Kernel 0a: convert encoder_outputs fp32 -> bf16 packed
// each thread: 2 float4 -> 1 uint4
// ============================================================
__global__ void cvtA_kernel(const float4* __restrict__ enc) {
    size_t idx = (size_t)blockIdx.x * 256 + threadIdx.x;   // over ROWS*EDIM/8
    float4 f0 = enc[idx * 2];
    float4 f1 = enc[idx * 2 + 1];
    uint4 o;
    o.x = pack_bf16x2(f0.x, f0.y);
    o.y = pack_bf16x2(f0.z, f0.w);
    o.z = pack_bf16x2(f1.x, f1.y);
    o.w = pack_bf16x2(f1.z, f1.w);
    g_enc_bf16[idx] = o;
}

// ============================================================
// Kernel 0b: convert w_e = attn_w[:, HID:3H] fp32 -> bf16 packed
// ============================================================
__global__ void cvtB_kernel(const float* __restrict__ attn_w) {
    size_t idx = (size_t)blockIdx.x * 256 + threadIdx.x;   // over HID*EDIM/8
    int h  = (int)(idx >> 8);          // EDIM/8 = 256 uint4 per row
    int j8 = (int)(idx & 255);
    const float4* src = (const float4*)(attn_w + (size_t)h * (3 * HID) + HID) + j8 * 2;
    float4 f0 = src[0];
    float4 f1 = src[1];
    uint4 o;
    o.x = pack_bf16x2(f0.x, f0.y);
    o.y = pack_bf16x2(f0.z, f0.w);
    o.z = pack_bf16x2(f1.x, f1.y);
    o.w = pack_bf16x2(f1.z, f1.w);
    g_we_bf16[idx] = o;
}

// ============================================================
// Kernel 1: hid_proj[b,h] = hidden[b,:] . attn_w[h, 0:H] + attn_b[h]  (fp32 exact)
// ============================================================
__global__ void hidproj_kernel(const float* __restrict__ hidden,
                               const float* __restrict__ attn_w,
                               const float* __restrict__ attn_b) {
    int b    = blockIdx.y;
    int warp = threadIdx.x >> 5;
    int lane = threadIdx.x & 31;
    int h    = blockIdx.x * 8 + warp;

    const float4* hv = (const float4*)(hidden + (size_t)b * HID);
    const float4* wv = (const float4*)(attn_w + (size_t)h * (3 * HID));

    float s = 0.f;
#pragma unroll
    for (int i = 0; i < HID / 4 / 32; i++) {
        float4 a = hv[lane + i * 32];
        float4 w = wv[lane + i * 32];
        s += a.x * w.x + a.y * w.y + a.z * w.z + a.w * w.w;
    }
#pragma unroll
    for (int o = 16; o; o >>= 1) s += __shfl_xor_sync(0xffffffffu, s, o);
    if (lane == 0) g_hid_proj[b * HID + h] = s + attn_b[h];
}

// ============================================================
// Kernel 2: zero scores
// ============================================================
__global__ void zero_scores_kernel() {
    g_scores[blockIdx.x * 1024 + threadIdx.x] = 0.f;
}

// ============================================================
// Kernel 3: scores via mma.sync bf16 m16n8k16, fused tanh + v-dot epilogue
// BM=128, BN=256, BK=64 (32 bf16x2 words). 256 threads (8 warps, 2x4),
// warp tile 64x64. 3-stage cp.async pipeline from pre-converted bf16 global.
// grid (4 n-tiles [x fast], 512 row-tiles [y]); 1 CTA/SM (168 KB smem).
// ============================================================
#define BM  128
#define BN  256
#define BKE 64               // k elements per tile
#define BKW 32               // bf16x2 words per tile-row
#define NKT (EDIM / BKE)     // 32
#define LDA 36               // padded row length in words

#define ABUF  (BM * LDA * 4)             // 18432 B
#define BBUF  (BN * LDA * 4)             // 36864 B
#define SM_A   0
#define SM_B   (3 * ABUF)                // 55296
#define SM_HP  (SM_B + 3 * BBUF)         // 165888
#define SM_VW  (SM_HP + BN * 4)          // 166912
#define SM_SSC (SM_VW + BN * 4)          // 167936
#define SM_SZ  (SM_SSC + BM * 4)         // 168448

__device__ __forceinline__ void stage_bf16(uint32_t aBuf, uint32_t bBuf,
                                           int m_base, int nb, int kt, int tid) {
    const char* Ab = (const char*)g_enc_bf16 + ((size_t)m_base * EDIM + kt * BKE) * 2;
    const char* Bb = (const char*)g_we_bf16 + ((size_t)nb * EDIM + kt * BKE) * 2;
    const int r0 = tid >> 3;
    const int c  = tid & 7;
#pragma unroll
    for (int i = 0; i < 4; i++) {                        // A: 128 rows
        int row = r0 + i * 32;
        cp16(aBuf + (row * LDA + c * 4) * 4, Ab + (size_t)row * (EDIM * 2) + c * 16);
    }
#pragma unroll
    for (int i = 0; i < 8; i++) {                        // B: 256 rows
        int row = r0 + i * 32;
        cp16(bBuf + (row * LDA + c * 4) * 4, Bb + (size_t)row * (EDIM * 2) + c * 16);
    }
}

__global__ __launch_bounds__(256, 1)
void scores_bf16_kernel(const float* __restrict__ v_w) {
    extern __shared__ char smem[];
    const uint32_t sb = smem_u32(smem);

    const int tid    = threadIdx.x;
    const int lane   = tid & 31;
    const int wid    = tid >> 5;
    const int warp_m = wid & 1;          // 0..1 (64 rows each)
    const int warp_n = wid >> 1;         // 0..3 (64 cols each)

    const int rt     = blockIdx.y;       // 0..511
    const int b      = rt >> 4;
    const int nb     = blockIdx.x * BN;  // 0..3 n-tiles
    const int m_base = rt * BM;

    float* hp_s = (float*)(smem + SM_HP);
    float* vw_s = (float*)(smem + SM_VW);
    float* ssc  = (float*)(smem + SM_SSC);
    hp_s[tid] = g_hid_proj[b * HID + nb + tid];
    vw_s[tid] = v_w[nb + tid];
    if (tid < BM) ssc[tid] = 0.f;

    // prologue: stage kt 0,1
    stage_bf16(sb + SM_A, sb + SM_B, m_base, nb, 0, tid);
    cp_commit();
    stage_bf16(sb + SM_A + ABUF, sb + SM_B + BBUF, m_base, nb, 1, tid);
    cp_commit();

    float acc[4][8][4];
#pragma unroll
    for (int mt = 0; mt < 4; mt++)
#pragma unroll
        for (int nt = 0; nt < 8; nt++)
#pragma unroll
            for (int j = 0; j < 4; j++) acc[mt][nt][j] = 0.f;

    for (int kt = 0; kt < NKT; kt++) {
        cp_wait1();              // stage kt complete
        __syncthreads();
        if (kt + 2 < NKT) {
            int nxt = (kt + 2) % 3;
            stage_bf16(sb + SM_A + nxt * ABUF, sb + SM_B + nxt * BBUF,
                       m_base, nb, kt + 2, tid);
        }
        cp_commit();

        const int cur = kt % 3;
        const uint32_t* Aw = (const uint32_t*)(smem + SM_A + cur * ABUF);
        const uint32_t* Bw = (const uint32_t*)(smem + SM_B + cur * BBUF);

#pragma unroll
        for (int kk = 0; kk < 4; kk++) {
            const int wc = kk * 8 + (lane & 3);
            uint32_t a[4][4];
#pragma unroll
            for (int mt = 0; mt < 4; mt++) {
                int r = warp_m * 64 + mt * 16 + (lane >> 2);
                a[mt][0] = Aw[r * LDA + wc];
                a[mt][1] = Aw[(r + 8) * LDA + wc];
                a[mt][2] = Aw[r * LDA + wc + 4];
                a[mt][3] = Aw[(r + 8) * LDA + wc + 4];
            }
#pragma unroll
            for (int nt = 0; nt < 8; nt++) {
                int n = warp_n * 64 + nt * 8 + (lane >> 2);
                uint32_t b0 = Bw[n * LDA + wc];
                uint32_t b1 = Bw[n * LDA + wc + 4];
#pragma unroll
                for (int mt = 0; mt < 4; mt++)
                    mma16816(acc[mt][nt], a[mt], b0, b1);
            }
        }
        __syncthreads();         // reads of buf 'cur' done before it is restaged
    }

    // ---- epilogue: tanh + v-dot (fp32), quad reduce, shared + global atomics ----
#pragma unroll
    for (int mt = 0; mt < 4; mt++) {
        float p0 = 0.f, p1 = 0.f;
#pragma unroll
        for (int nt = 0; nt < 8; nt++) {
            int c0 = warp_n * 64 + nt * 8 + 2 * (lane & 3);
            float v0 = vw_s[c0], v1 = vw_s[c0 + 1];
            float h0 = hp_s[c0], h1 = hp_s[c0 + 1];
            p0 += v0 * tanhf(h0 + acc[mt][nt][0]) + v1 * tanhf(h1 + acc[mt][nt][1]);
            p1 += v0 * tanhf(h0 + acc[mt][nt][2]) + v1 * tanhf(h1 + acc[mt][nt][3]);
        }
        p0 += __shfl_xor_sync(0xffffffffu, p0, 1);
        p0 += __shfl_xor_sync(0xffffffffu, p0, 2);
        p1 += __shfl_xor_sync(0xffffffffu, p1, 1);
        p1 += __shfl_xor_sync(0xffffffffu, p1, 2);
        if ((lane & 3) == 0) {
            int r = warp_m * 64 + mt * 16 + (lane >> 2);
            atomicAdd(&ssc[r], p0);
            atomicAdd(&ssc[r + 8], p1);
        }
    }
    __syncthreads();
    if (tid < BM) atomicAdd(&g_scores[m_base + tid], ssc[tid]);
}

// ============================================================
// Kernel 4: softmax over S per batch
// ============================================================
__global__ void softmax_kernel(float* __restrict__ out_w) {
    __shared__ float red[256];
    int b = blockIdx.x;
    int tid = threadIdx.x;

    float vals[8];
    float mx = -1e30f;
#pragma unroll
    for (int i = 0; i < 8; i++) {
        vals[i] = g_scores[b * SEQ + tid + i * 256];
        mx = fmaxf(mx, vals[i]);
    }
    red[tid] = mx;
    __syncthreads();
    for (int o = 128; o; o >>= 1) {
        if (tid < o) red[tid] = fmaxf(red[tid], red[tid + o]);
        __syncthreads();
    }
    mx = red[0];
    __syncthreads();

    float s = 0.f;
#pragma unroll
    for (int i = 0; i < 8; i++) {
        vals[i] = expf(vals[i] - mx);
        s += vals[i];
    }
    red[tid] = s;
    __syncthreads();
    for (int o = 128; o; o >>= 1) {
        if (tid < o) red[tid] += red[tid + o];
        __syncthreads();
    }
    float inv = 1.f / red[0];
#pragma unroll
    for (int i = 0; i < 8; i++)
        out_w[b * SEQ + tid + i * 256] = vals[i] * inv;
}

// ============================================================
// Kernel 5: context[b,e] = sum_s w[b,s] * enc[b,s,e]   (fp32 exact)
// ============================================================
__global__ void context_kernel(const float* __restrict__ enc,
                               const float* __restrict__ w,
                               float* __restrict__ outc) {
    __shared__ float ws[SEQ];
    int b = blockIdx.y;
    int e = blockIdx.x * 256 + threadIdx.x;

    for (int i = threadIdx.x; i < SEQ; i += 256) ws[i] = w[b * SEQ + i];
    __syncthreads();

    const float* ep = enc + (size_t)b * SEQ * EDIM + e;
    float a0 = 0.f, a1 = 0.f, a2 = 0.f, a3 = 0.f;
    for (int s = 0; s < SEQ; s += 4) {
        a0 += ws[s + 0] * ep[(size_t)(s + 0) * EDIM];
        a1 += ws[s + 1] * ep[(size_t)(s + 1) * EDIM];
        a2 += ws[s + 2] * ep[(size_t)(s + 2) * EDIM];
        a3 += ws[s + 3] * ep[(size_t)(s + 3) * EDIM];
    }
    outc[b * EDIM + e] = (a0 + a1) + (a2 + a3);
}

// ============================================================
// launch
// ============================================================
extern "C" void kernel_launch(void* const* d_in, const int* in_sizes, int n_in,
                              void* d_out, int out_size) {
    const float* hidden = (const float*)d_in[0];
    const float* enc    = (const float*)d_in[1];
    const float* attn_w = (const float*)d_in[2];
    const float* attn_b = (const float*)d_in[3];
    const float* v_w    = (const float*)d_in[4];

    float* out_ctx = (float*)d_out;                  // [32, 2048]
    float* out_wts = (float*)d_out + BATCH * EDIM;   // [32, 2048]

    cudaFuncSetAttribute(scores_bf16_kernel,
                         cudaFuncAttributeMaxDynamicSharedMemorySize, SM_SZ);

    cvtA_kernel<<<(int)((size_t)ROWS * EDIM / 8 / 256), 256>>>((const float4*)enc);
    cvtB_kernel<<<(int)((size_t)HID * EDIM / 8 / 256), 256>>>(attn_w);
    hidproj_kernel<<<dim3(HID / 8, BATCH), 256>>>(hidden, attn_w, attn_b);
    zero_scores_kernel<<<(BATCH * SEQ) / 1024, 1024>>>();
    scores_bf16_kernel<<<dim3(HID / BN, ROWS / BM), 256, SM_SZ>>>(v_w);
    softmax_kernel<<<BATCH, 256>>>(out_wts);
    context_kernel<<<dim3(EDIM / 256, BATCH), 256>>>(enc, out_wts, out_ctx);
}